// round 3
// baseline (speedup 1.0000x reference)
#include <cuda_runtime.h>
#include <cstdint>

#define NN   100000
#define NE   800000
#define F0   128
#define C1   256
#define C2   128
#define NOUT 6

// ---------------- scratch (device globals: allocation-free rule) ------------
__device__ float    g_xw [(size_t)NN * C1];
__device__ float    g_agg[(size_t)NN * C1];
__device__ float    g_h2 [(size_t)NN * C2];
__device__ float    g_as [NN];
__device__ float    g_ad [NN];
__device__ unsigned g_emax[NN];
__device__ float    g_den[NN];
__device__ float    g_e  [NN + NE];

// ---------------- orderable float encoding for atomicMax --------------------
__device__ __forceinline__ unsigned fenc(float f) {
    unsigned u = __float_as_uint(f);
    return (u & 0x80000000u) ? ~u : (u | 0x80000000u);
}
__device__ __forceinline__ float fdec(unsigned u) {
    return (u & 0x80000000u) ? __uint_as_float(u ^ 0x80000000u)
                             : __uint_as_float(~u);
}

// ---------------- generic fp32 SGEMM: C = f(A') @ B  ------------------------
// A': optionally relu(A + bias_in[k]) ; C: optionally relu(C + bias_out[n])
// BM=128 BN=64 BK=16 TM=8 TN=4, 256 threads.
template<int BM, int BN, int BK, int TM, int TN, bool IN_RB, bool OUT_B, bool OUT_R>
__global__ void __launch_bounds__(256, 2)
sgemm(const float* __restrict__ A, const float* __restrict__ B,
      const float* __restrict__ bin, const float* __restrict__ bout,
      float* __restrict__ C, int M, int N, int K)
{
    __shared__ float As[BK][BM + 4];
    __shared__ float Bs[BK][BN];
    const int tid = threadIdx.x;
    const int bm0 = blockIdx.y * BM;
    const int bn0 = blockIdx.x * BN;
    const int tx  = tid % (BN / TN);   // 0..15
    const int ty  = tid / (BN / TN);   // 0..15

    float acc[TM][TN];
#pragma unroll
    for (int i = 0; i < TM; i++)
#pragma unroll
        for (int j = 0; j < TN; j++) acc[i][j] = 0.f;

    for (int k0 = 0; k0 < K; k0 += BK) {
        // A tile: BM x BK  (2 float4 per thread)
#pragma unroll
        for (int p = 0; p < (BM * BK) / (256 * 4); p++) {
            int id = tid + p * 256;
            int r  = id / (BK / 4);
            int c4 = (id % (BK / 4)) * 4;
            float4 v = make_float4(0.f, 0.f, 0.f, 0.f);
            if (bm0 + r < M)
                v = *(const float4*)&A[(size_t)(bm0 + r) * K + k0 + c4];
            if (IN_RB) {
                v.x = fmaxf(v.x + bin[k0 + c4 + 0], 0.f);
                v.y = fmaxf(v.y + bin[k0 + c4 + 1], 0.f);
                v.z = fmaxf(v.z + bin[k0 + c4 + 2], 0.f);
                v.w = fmaxf(v.w + bin[k0 + c4 + 3], 0.f);
            }
            As[c4 + 0][r] = v.x;
            As[c4 + 1][r] = v.y;
            As[c4 + 2][r] = v.z;
            As[c4 + 3][r] = v.w;
        }
        // B tile: BK x BN  (1 float4 per thread)
#pragma unroll
        for (int p = 0; p < (BK * BN) / (256 * 4); p++) {
            int id = tid + p * 256;
            int r  = id / (BN / 4);
            int c4 = (id % (BN / 4)) * 4;
            *(float4*)&Bs[r][c4] =
                *(const float4*)&B[(size_t)(k0 + r) * N + bn0 + c4];
        }
        __syncthreads();

#pragma unroll
        for (int kk = 0; kk < BK; kk++) {
            float ra[TM], rb[TN];
#pragma unroll
            for (int i = 0; i < TM; i++) ra[i] = As[kk][ty * TM + i];
#pragma unroll
            for (int j = 0; j < TN; j++) rb[j] = Bs[kk][tx * TN + j];
#pragma unroll
            for (int i = 0; i < TM; i++)
#pragma unroll
                for (int j = 0; j < TN; j++)
                    acc[i][j] += ra[i] * rb[j];
        }
        __syncthreads();
    }

#pragma unroll
    for (int i = 0; i < TM; i++) {
        int row = bm0 + ty * TM + i;
        if (row < M) {
            int col = bn0 + tx * TN;
            float4 v;
            float* pv = &v.x;
#pragma unroll
            for (int j = 0; j < TN; j++) {
                float c = acc[i][j];
                if (OUT_B) c += bout[col + j];
                if (OUT_R) c = fmaxf(c, 0.f);
                pv[j] = c;
            }
            *(float4*)&C[(size_t)row * N + col] = v;
        }
    }
}

// ---------------- per-node attention halves ---------------------------------
__global__ void alpha_kernel(const float* __restrict__ a_src,
                             const float* __restrict__ a_dst, int n)
{
    int warp = (blockIdx.x * blockDim.x + threadIdx.x) >> 5;
    int lane = threadIdx.x & 31;
    if (warp >= n) return;
    const float4* row = (const float4*)&g_xw[(size_t)warp * C1];
    const float4* asv = (const float4*)a_src;
    const float4* adv = (const float4*)a_dst;
    float s = 0.f, d = 0.f;
#pragma unroll
    for (int h = 0; h < 2; h++) {
        float4 v  = row[lane + h * 32];
        float4 as = __ldg(&asv[lane + h * 32]);
        float4 ad = __ldg(&adv[lane + h * 32]);
        s += v.x * as.x + v.y * as.y + v.z * as.z + v.w * as.w;
        d += v.x * ad.x + v.y * ad.y + v.z * ad.z + v.w * ad.w;
    }
#pragma unroll
    for (int o = 16; o > 0; o >>= 1) {
        s += __shfl_down_sync(0xffffffffu, s, o);
        d += __shfl_down_sync(0xffffffffu, d, o);
    }
    if (lane == 0) { g_as[warp] = s; g_ad[warp] = d; }
}

// ---------------- edge pass 1: raw score + segment max ----------------------
__global__ void edge_max(const int* __restrict__ ei, int E, int n)
{
    int i = blockIdx.x * blockDim.x + threadIdx.x;
    if (i >= E + n) return;
    int s, d;
    if (i < E) { s = __ldg(&ei[i]); d = __ldg(&ei[E + i]); } else { s = d = i - E; }
    float e = g_as[s] + g_ad[d];
    e = e > 0.f ? e : 0.2f * e;          // LeakyReLU(0.2)
    g_e[i] = e;
    atomicMax(&g_emax[d], fenc(e));
}

// ---------------- edge pass 2: exp + denom ----------------------------------
__global__ void edge_exp(const int* __restrict__ ei, int E, int n)
{
    int i = blockIdx.x * blockDim.x + threadIdx.x;
    if (i >= E + n) return;
    int d = (i < E) ? __ldg(&ei[E + i]) : (i - E);
    float e = __expf(g_e[i] - fdec(g_emax[d]));
    g_e[i] = e;
    atomicAdd(&g_den[d], e);
}

// ---------------- edge pass 3: weighted scatter (1 warp / edge) -------------
__global__ void edge_scatter(const int* __restrict__ ei, int E, int n)
{
    int warp = (int)(((size_t)blockIdx.x * blockDim.x + threadIdx.x) >> 5);
    int lane = threadIdx.x & 31;
    if (warp >= E + n) return;
    int s, d;
    float w;
    if (lane == 0) {
        if (warp < E) { s = __ldg(&ei[warp]); d = __ldg(&ei[E + warp]); }
        else          { s = d = warp - E; }
        w = g_e[warp] / g_den[d];
    }
    s = __shfl_sync(0xffffffffu, s, 0);
    d = __shfl_sync(0xffffffffu, d, 0);
    w = __shfl_sync(0xffffffffu, w, 0);
    const float4* src = (const float4*)&g_xw[(size_t)s * C1];
    float*        dp  = &g_agg[(size_t)d * C1];
#pragma unroll
    for (int h = 0; h < 2; h++) {
        float4 v = src[lane + h * 32];
        float* p = dp + (size_t)(lane + h * 32) * 4;
        asm volatile("red.global.add.v4.f32 [%0], {%1,%2,%3,%4};"
                     :: "l"(p), "f"(v.x * w), "f"(v.y * w),
                        "f"(v.z * w), "f"(v.w * w)
                     : "memory");
    }
}

// ---------------- final tiny GEMM: out = h2 @ W_out + b_out -----------------
__global__ void out_kernel(const float* __restrict__ Wout,
                           const float* __restrict__ bout,
                           float* __restrict__ out, int n)
{
    __shared__ float sw[C2 * NOUT];
    for (int i = threadIdx.x; i < C2 * NOUT; i += blockDim.x) sw[i] = Wout[i];
    __syncthreads();
    int warp = (blockIdx.x * blockDim.x + threadIdx.x) >> 5;
    int lane = threadIdx.x & 31;
    if (warp >= n) return;
    float4 v = ((const float4*)&g_h2[(size_t)warp * C2])[lane];
    float p[NOUT];
#pragma unroll
    for (int o = 0; o < NOUT; o++) {
        p[o] = v.x * sw[(lane * 4 + 0) * NOUT + o]
             + v.y * sw[(lane * 4 + 1) * NOUT + o]
             + v.z * sw[(lane * 4 + 2) * NOUT + o]
             + v.w * sw[(lane * 4 + 3) * NOUT + o];
    }
#pragma unroll
    for (int o = 0; o < NOUT; o++)
#pragma unroll
        for (int sh = 16; sh > 0; sh >>= 1)
            p[o] += __shfl_down_sync(0xffffffffu, p[o], sh);
    if (lane == 0) {
#pragma unroll
        for (int o = 0; o < NOUT; o++)
            out[(size_t)warp * NOUT + o] = p[o] + bout[o];
    }
}

// ---------------- launch ----------------------------------------------------
extern "C" void kernel_launch(void* const* d_in, const int* in_sizes, int n_in,
                              void* d_out, int out_size)
{
    const float* x     = (const float*)d_in[0];
    const int*   ei    = (const int*)  d_in[1];
    const float* W     = (const float*)d_in[2];
    const float* a_src = (const float*)d_in[3];
    const float* a_dst = (const float*)d_in[4];
    const float* b     = (const float*)d_in[5];
    const float* W2    = (const float*)d_in[6];
    const float* b2    = (const float*)d_in[7];
    const float* Wo    = (const float*)d_in[8];
    const float* bo    = (const float*)d_in[9];

    const int n = in_sizes[0] / F0;   // 100000
    const int E = in_sizes[1] / 2;    // 800000
    const int tot = E + n;

    float *xw, *agg, *h2, *den;
    unsigned *emax;
    cudaGetSymbolAddress((void**)&xw,   g_xw);
    cudaGetSymbolAddress((void**)&agg,  g_agg);
    cudaGetSymbolAddress((void**)&h2,   g_h2);
    cudaGetSymbolAddress((void**)&den,  g_den);
    cudaGetSymbolAddress((void**)&emax, g_emax);

    // GEMM1: xw = x @ W          [n,128]x[128,256]
    {
        dim3 grid(C1 / 64, (n + 127) / 128);
        sgemm<128, 64, 16, 8, 4, false, false, false>
            <<<grid, 256>>>(x, W, nullptr, nullptr, xw, n, C1, F0);
    }
    // zero agg / den / emax (async memsets are graph-capturable)
    cudaMemsetAsync(agg,  0, (size_t)n * C1 * sizeof(float));
    cudaMemsetAsync(den,  0, (size_t)n * sizeof(float));
    cudaMemsetAsync(emax, 0, (size_t)n * sizeof(unsigned));
    // per-node attention halves
    alpha_kernel<<<(n * 32 + 255) / 256, 256>>>(a_src, a_dst, n);
    // edge softmax
    edge_max    <<<(tot + 255) / 256, 256>>>(ei, E, n);
    edge_exp    <<<(tot + 255) / 256, 256>>>(ei, E, n);
    // weighted scatter aggregate (1 warp per edge)
    {
        size_t threads = (size_t)tot * 32;
        edge_scatter<<<(unsigned)((threads + 255) / 256), 256>>>(ei, E, n);
    }
    // GEMM2: h2 = relu(relu(agg + b) @ W2 + b2)   [n,256]x[256,128]
    {
        dim3 grid(C2 / 64, (n + 127) / 128);
        sgemm<128, 64, 16, 8, 4, true, true, true>
            <<<grid, 256>>>(agg, W2, b, b2, h2, n, C2, C1);
    }
    // out = h2 @ W_out + b_out
    out_kernel<<<(n * 32 + 255) / 256, 256>>>(Wo, bo, (float*)d_out, n);
}

// round 4
// speedup vs baseline: 1.0354x; 1.0354x over previous
#include <cuda_runtime.h>
#include <cstdint>

#define NN   100000
#define NE   800000
#define F0   128
#define C1   256
#define C2   128
#define NOUT 6

// ---------------- scratch (device globals: allocation-free rule) ------------
__device__ float g_xw [(size_t)NN * C1];
__device__ float g_agg[(size_t)NN * C1];
__device__ float g_as [NN];
__device__ float g_ad [NN];
__device__ float g_den[NN];
__device__ float g_e  [NN + NE];

// ============================================================================
// GEMM1: xw = x @ W   [M,128]x[128,256], fused alpha epilogue:
//   g_as[row] += xw_row . a_src ; g_ad[row] += xw_row . a_dst  (atomic partials)
// Tiles: BM=128 BN=128 BK=16, TM=TN=8, 256 thr, double-buffered, 1 sync/iter.
// ============================================================================
__global__ void __launch_bounds__(256, 2)
gemm1_kernel(const float* __restrict__ A, const float* __restrict__ B,
             const float* __restrict__ a_src, const float* __restrict__ a_dst,
             float* __restrict__ C, int M)
{
    const int K = F0, N = C1, KB = K / 16;
    __shared__ float As[2][16][128 + 4];
    __shared__ float Bs[2][16][128];

    const int tid = threadIdx.x;
    const int bm0 = blockIdx.y * 128;
    const int bn0 = blockIdx.x * 128;
    const int tx  = tid & 15;          // 0..15 (within half-warp)
    const int ty  = tid >> 4;          // 0..15

    const int ar = tid >> 2, ac = (tid & 3) * 4;   // A loader: 64 rows/pass
    const int br = tid >> 5, bc = (tid & 31) * 4;  // B loader: 8 rows/pass

    float4 aR[2], bR[2];
    // prologue: load k-tile 0
#pragma unroll
    for (int p = 0; p < 2; p++) {
        int r = ar + p * 64;
        aR[p] = (bm0 + r < M) ? *(const float4*)&A[(size_t)(bm0 + r) * K + ac]
                              : make_float4(0.f, 0.f, 0.f, 0.f);
        bR[p] = *(const float4*)&B[(size_t)(br + p * 8) * N + bn0 + bc];
    }
#pragma unroll
    for (int p = 0; p < 2; p++) {
        int r = ar + p * 64;
        As[0][ac + 0][r] = aR[p].x; As[0][ac + 1][r] = aR[p].y;
        As[0][ac + 2][r] = aR[p].z; As[0][ac + 3][r] = aR[p].w;
        *(float4*)&Bs[0][br + p * 8][bc] = bR[p];
    }
    __syncthreads();

    float acc[8][8];
#pragma unroll
    for (int i = 0; i < 8; i++)
#pragma unroll
        for (int j = 0; j < 8; j++) acc[i][j] = 0.f;

    for (int kb = 0; kb < KB; kb++) {
        int cur = kb & 1, nxt = cur ^ 1;
        if (kb + 1 < KB) {
            int k0 = (kb + 1) * 16;
#pragma unroll
            for (int p = 0; p < 2; p++) {
                int r = ar + p * 64;
                aR[p] = (bm0 + r < M)
                      ? *(const float4*)&A[(size_t)(bm0 + r) * K + k0 + ac]
                      : make_float4(0.f, 0.f, 0.f, 0.f);
                bR[p] = *(const float4*)&B[(size_t)(k0 + br + p * 8) * N + bn0 + bc];
            }
        }
#pragma unroll
        for (int kk = 0; kk < 16; kk++) {
            float4 ra0 = *(float4*)&As[cur][kk][ty * 8];
            float4 ra1 = *(float4*)&As[cur][kk][ty * 8 + 4];
            float4 rb0 = *(float4*)&Bs[cur][kk][tx * 8];
            float4 rb1 = *(float4*)&Bs[cur][kk][tx * 8 + 4];
            float ra[8] = {ra0.x, ra0.y, ra0.z, ra0.w, ra1.x, ra1.y, ra1.z, ra1.w};
            float rb[8] = {rb0.x, rb0.y, rb0.z, rb0.w, rb1.x, rb1.y, rb1.z, rb1.w};
#pragma unroll
            for (int i = 0; i < 8; i++)
#pragma unroll
                for (int j = 0; j < 8; j++)
                    acc[i][j] += ra[i] * rb[j];
        }
        if (kb + 1 < KB) {
#pragma unroll
            for (int p = 0; p < 2; p++) {
                int r = ar + p * 64;
                As[nxt][ac + 0][r] = aR[p].x; As[nxt][ac + 1][r] = aR[p].y;
                As[nxt][ac + 2][r] = aR[p].z; As[nxt][ac + 3][r] = aR[p].w;
                *(float4*)&Bs[nxt][br + p * 8][bc] = bR[p];
            }
        }
        __syncthreads();
    }

    // epilogue: store C + alpha partials
    float asv[8], adv[8];
#pragma unroll
    for (int j = 0; j < 8; j++) {
        int col = bn0 + tx * 8 + j;
        asv[j] = __ldg(&a_src[col]);
        adv[j] = __ldg(&a_dst[col]);
    }
#pragma unroll
    for (int i = 0; i < 8; i++) {
        int row = bm0 + ty * 8 + i;
        float s = 0.f, d = 0.f;
#pragma unroll
        for (int j = 0; j < 8; j++) { s += acc[i][j] * asv[j]; d += acc[i][j] * adv[j]; }
#pragma unroll
        for (int o = 8; o > 0; o >>= 1) {
            s += __shfl_down_sync(0xffffffffu, s, o, 16);
            d += __shfl_down_sync(0xffffffffu, d, o, 16);
        }
        if (row < M) {
            int col = bn0 + tx * 8;
            *(float4*)&C[(size_t)row * N + col]     =
                make_float4(acc[i][0], acc[i][1], acc[i][2], acc[i][3]);
            *(float4*)&C[(size_t)row * N + col + 4] =
                make_float4(acc[i][4], acc[i][5], acc[i][6], acc[i][7]);
            if (tx == 0) { atomicAdd(&g_as[row], s); atomicAdd(&g_ad[row], d); }
        }
    }
}

// ============================================================================
// GEMM2: out = relu( relu(agg + b) @ W2 + b2 ) @ Wo + bo
// [M,256]x[256,128] with fused final [128,6] projection. h2 never stored.
// grid = (1, ceil(M/128)) — each block owns full 128-wide h2 rows.
// ============================================================================
__global__ void __launch_bounds__(256, 2)
gemm2_kernel(const float* __restrict__ A, const float* __restrict__ B,
             const float* __restrict__ bin, const float* __restrict__ bout,
             const float* __restrict__ Wo, const float* __restrict__ bo,
             float* __restrict__ out, int M)
{
    const int K = C1, N = C2, KB = K / 16;
    __shared__ float As[2][16][128 + 4];
    __shared__ float Bs[2][16][128];
    __shared__ float sWo[C2 * NOUT];

    const int tid = threadIdx.x;
    const int bm0 = blockIdx.y * 128;
    const int tx  = tid & 15;
    const int ty  = tid >> 4;

    const int ar = tid >> 2, ac = (tid & 3) * 4;
    const int br = tid >> 5, bc = (tid & 31) * 4;

    for (int i = tid; i < C2 * NOUT; i += 256) sWo[i] = Wo[i];

    float4 aR[2], bR[2];
#pragma unroll
    for (int p = 0; p < 2; p++) {
        int r = ar + p * 64;
        float4 v = (bm0 + r < M) ? *(const float4*)&A[(size_t)(bm0 + r) * K + ac]
                                 : make_float4(0.f, 0.f, 0.f, 0.f);
        v.x = fmaxf(v.x + __ldg(&bin[ac + 0]), 0.f);
        v.y = fmaxf(v.y + __ldg(&bin[ac + 1]), 0.f);
        v.z = fmaxf(v.z + __ldg(&bin[ac + 2]), 0.f);
        v.w = fmaxf(v.w + __ldg(&bin[ac + 3]), 0.f);
        aR[p] = v;
        bR[p] = *(const float4*)&B[(size_t)(br + p * 8) * N + bc];
    }
#pragma unroll
    for (int p = 0; p < 2; p++) {
        int r = ar + p * 64;
        As[0][ac + 0][r] = aR[p].x; As[0][ac + 1][r] = aR[p].y;
        As[0][ac + 2][r] = aR[p].z; As[0][ac + 3][r] = aR[p].w;
        *(float4*)&Bs[0][br + p * 8][bc] = bR[p];
    }
    __syncthreads();

    float acc[8][8];
#pragma unroll
    for (int i = 0; i < 8; i++)
#pragma unroll
        for (int j = 0; j < 8; j++) acc[i][j] = 0.f;

    for (int kb = 0; kb < KB; kb++) {
        int cur = kb & 1, nxt = cur ^ 1;
        if (kb + 1 < KB) {
            int k0 = (kb + 1) * 16;
#pragma unroll
            for (int p = 0; p < 2; p++) {
                int r = ar + p * 64;
                float4 v = (bm0 + r < M)
                         ? *(const float4*)&A[(size_t)(bm0 + r) * K + k0 + ac]
                         : make_float4(0.f, 0.f, 0.f, 0.f);
                v.x = fmaxf(v.x + __ldg(&bin[k0 + ac + 0]), 0.f);
                v.y = fmaxf(v.y + __ldg(&bin[k0 + ac + 1]), 0.f);
                v.z = fmaxf(v.z + __ldg(&bin[k0 + ac + 2]), 0.f);
                v.w = fmaxf(v.w + __ldg(&bin[k0 + ac + 3]), 0.f);
                aR[p] = v;
                bR[p] = *(const float4*)&B[(size_t)(k0 + br + p * 8) * N + bc];
            }
        }
#pragma unroll
        for (int kk = 0; kk < 16; kk++) {
            float4 ra0 = *(float4*)&As[cur][kk][ty * 8];
            float4 ra1 = *(float4*)&As[cur][kk][ty * 8 + 4];
            float4 rb0 = *(float4*)&Bs[cur][kk][tx * 8];
            float4 rb1 = *(float4*)&Bs[cur][kk][tx * 8 + 4];
            float ra[8] = {ra0.x, ra0.y, ra0.z, ra0.w, ra1.x, ra1.y, ra1.z, ra1.w};
            float rb[8] = {rb0.x, rb0.y, rb0.z, rb0.w, rb1.x, rb1.y, rb1.z, rb1.w};
#pragma unroll
            for (int i = 0; i < 8; i++)
#pragma unroll
                for (int j = 0; j < 8; j++)
                    acc[i][j] += ra[i] * rb[j];
        }
        if (kb + 1 < KB) {
#pragma unroll
            for (int p = 0; p < 2; p++) {
                int r = ar + p * 64;
                As[nxt][ac + 0][r] = aR[p].x; As[nxt][ac + 1][r] = aR[p].y;
                As[nxt][ac + 2][r] = aR[p].z; As[nxt][ac + 3][r] = aR[p].w;
                *(float4*)&Bs[nxt][br + p * 8][bc] = bR[p];
            }
        }
        __syncthreads();
    }

    // epilogue: relu(h2) then project to 6 outputs, reduce over tx, store
    float b2c[8];
#pragma unroll
    for (int j = 0; j < 8; j++) b2c[j] = __ldg(&bout[tx * 8 + j]);
#pragma unroll
    for (int i = 0; i < 8; i++) {
        int row = bm0 + ty * 8 + i;
        float r[8];
#pragma unroll
        for (int j = 0; j < 8; j++) r[j] = fmaxf(acc[i][j] + b2c[j], 0.f);
        float po[NOUT];
#pragma unroll
        for (int o = 0; o < NOUT; o++) {
            float p = 0.f;
#pragma unroll
            for (int j = 0; j < 8; j++) p += r[j] * sWo[(tx * 8 + j) * NOUT + o];
#pragma unroll
            for (int off = 8; off > 0; off >>= 1)
                p += __shfl_down_sync(0xffffffffu, p, off, 16);
            po[o] = p;
        }
        if (tx == 0 && row < M) {
#pragma unroll
            for (int o = 0; o < NOUT; o++)
                out[(size_t)row * NOUT + o] = po[o] + __ldg(&bo[o]);
        }
    }
}

// ---------------- edge pass 1: weight + denom (no max: scores are tiny) -----
__global__ void edge_weights(const int* __restrict__ ei, int E, int n)
{
    int i = blockIdx.x * blockDim.x + threadIdx.x;
    if (i >= E + n) return;
    int s, d;
    if (i < E) { s = __ldg(&ei[i]); d = __ldg(&ei[E + i]); } else { s = d = i - E; }
    float e = g_as[s] + g_ad[d];
    e = e > 0.f ? e : 0.2f * e;          // LeakyReLU(0.2)
    float w = __expf(e);
    g_e[i] = w;
    atomicAdd(&g_den[d], w);
}

// ---------------- edge pass 2: weighted scatter (1 warp / edge) -------------
__global__ void edge_scatter(const int* __restrict__ ei, int E, int n)
{
    int warp = (int)(((size_t)blockIdx.x * blockDim.x + threadIdx.x) >> 5);
    int lane = threadIdx.x & 31;
    if (warp >= E + n) return;
    int s, d;
    float w;
    if (lane == 0) {
        if (warp < E) { s = __ldg(&ei[warp]); d = __ldg(&ei[E + warp]); }
        else          { s = d = warp - E; }
        w = g_e[warp] / g_den[d];
    }
    s = __shfl_sync(0xffffffffu, s, 0);
    d = __shfl_sync(0xffffffffu, d, 0);
    w = __shfl_sync(0xffffffffu, w, 0);
    const float4* src = (const float4*)&g_xw[(size_t)s * C1];
    float*        dp  = &g_agg[(size_t)d * C1];
#pragma unroll
    for (int h = 0; h < 2; h++) {
        float4 v = src[lane + h * 32];
        float* p = dp + (size_t)(lane + h * 32) * 4;
        asm volatile("red.global.add.v4.f32 [%0], {%1,%2,%3,%4};"
                     :: "l"(p), "f"(v.x * w), "f"(v.y * w),
                        "f"(v.z * w), "f"(v.w * w)
                     : "memory");
    }
}

// ---------------- launch ----------------------------------------------------
extern "C" void kernel_launch(void* const* d_in, const int* in_sizes, int n_in,
                              void* d_out, int out_size)
{
    const float* x     = (const float*)d_in[0];
    const int*   ei    = (const int*)  d_in[1];
    const float* W     = (const float*)d_in[2];
    const float* a_src = (const float*)d_in[3];
    const float* a_dst = (const float*)d_in[4];
    const float* b     = (const float*)d_in[5];
    const float* W2    = (const float*)d_in[6];
    const float* b2    = (const float*)d_in[7];
    const float* Wo    = (const float*)d_in[8];
    const float* bo    = (const float*)d_in[9];

    const int n = in_sizes[0] / F0;   // 100000
    const int E = in_sizes[1] / 2;    // 800000
    const int tot = E + n;

    float *xw, *agg, *as_, *ad_, *den;
    cudaGetSymbolAddress((void**)&xw,  g_xw);
    cudaGetSymbolAddress((void**)&agg, g_agg);
    cudaGetSymbolAddress((void**)&as_, g_as);
    cudaGetSymbolAddress((void**)&ad_, g_ad);
    cudaGetSymbolAddress((void**)&den, g_den);

    // zero accumulators (async memsets are graph-capturable)
    cudaMemsetAsync(agg, 0, (size_t)n * C1 * sizeof(float));
    cudaMemsetAsync(as_, 0, (size_t)n * sizeof(float));
    cudaMemsetAsync(ad_, 0, (size_t)n * sizeof(float));
    cudaMemsetAsync(den, 0, (size_t)n * sizeof(float));

    // GEMM1 + fused alpha
    {
        dim3 grid(C1 / 128, (n + 127) / 128);
        gemm1_kernel<<<grid, 256>>>(x, W, a_src, a_dst, xw, n);
    }
    // edge softmax weights + denom
    edge_weights<<<(tot + 255) / 256, 256>>>(ei, E, n);
    // weighted scatter aggregate (1 warp per edge)
    {
        size_t threads = (size_t)tot * 32;
        edge_scatter<<<(unsigned)((threads + 255) / 256), 256>>>(ei, E, n);
    }
    // GEMM2 + fused output projection (writes d_out directly)
    {
        dim3 grid(1, (n + 127) / 128);
        gemm2_kernel<<<grid, 256>>>(agg, W2, b, b2, Wo, bo, (float*)d_out, n);
    }
}

// round 8
// speedup vs baseline: 1.4396x; 1.3904x over previous
#include <cuda_runtime.h>
#include <cstdint>

#define NN   100000
#define NE   800000
#define F0   128
#define C1   256
#define C2   128
#define NOUT 6

// ---------------- scratch (device globals: allocation-free rule) ------------
__device__ float g_xw [(size_t)NN * C1];
__device__ float g_agg[(size_t)NN * C1];
__device__ float g_as [NN];
__device__ float g_ad [NN];
__device__ float g_den[NN];
__device__ float g_e  [NN + NE];

// ---------------- tf32 helpers ----------------------------------------------
__device__ __forceinline__ uint32_t f2tf32(float f) {
    uint32_t u;
    asm("cvt.rna.tf32.f32 %0, %1;" : "=r"(u) : "f"(f));
    return u;
}
__device__ __forceinline__ void mma_tf32(float* c, const uint32_t* a, const uint32_t* b) {
    asm volatile(
        "mma.sync.aligned.m16n8k8.row.col.f32.tf32.tf32.f32 "
        "{%0,%1,%2,%3}, {%4,%5,%6,%7}, {%8,%9}, {%0,%1,%2,%3};"
        : "+f"(c[0]), "+f"(c[1]), "+f"(c[2]), "+f"(c[3])
        : "r"(a[0]), "r"(a[1]), "r"(a[2]), "r"(a[3]), "r"(b[0]), "r"(b[1]));
}

#define SA_LD 36     // sA row stride (floats): (4*qid+tq) banks all-distinct
#define SB_LD 136    // sB row stride (floats): (8*tq+qid) banks all-distinct

// ============================================================================
// GEMM1 (mma.sync tf32): xw = x @ W  [M,128]x[128,256]
// Fused: alpha partials g_as/g_ad (atomicAdd).
// BM=128 BN=128 BK=32, 8 warps = 2(M) x 4(N), warp tile 64x32.
// ============================================================================
__global__ void __launch_bounds__(256, 2)
gat_gemm1(const float* __restrict__ X, const float* __restrict__ W,
          const float* __restrict__ a_srcp, const float* __restrict__ a_dstp,
          float* __restrict__ XW, int M)
{
    __shared__ uint32_t sA[128 * SA_LD];
    __shared__ uint32_t sB[32 * SB_LD];
    __shared__ float sAs[128], sAd[128];

    const int tid   = threadIdx.x;
    const int lane  = tid & 31;
    const int wid   = tid >> 5;
    const int qid   = lane >> 2;      // 0..7
    const int tq    = lane & 3;       // 0..3
    const int warpM = wid & 1;        // 0..1
    const int warpN = wid >> 1;       // 0..3
    const int bm0   = blockIdx.y * 128;
    const int bn0   = blockIdx.x * 128;

    if (tid < 128) { sAs[tid] = a_srcp[bn0 + tid]; sAd[tid] = a_dstp[bn0 + tid]; }

    float acc[4][4][4];
#pragma unroll
    for (int i = 0; i < 4; i++)
#pragma unroll
        for (int j = 0; j < 4; j++)
#pragma unroll
            for (int q = 0; q < 4; q++) acc[i][j][q] = 0.f;

    const int arow = tid >> 1, acol = (tid & 1) * 16;   // A: 128x32, 2 thr/row
    const int brow = tid >> 3, bcol = (tid & 7) * 16;   // B: 32x128, 8 thr/row

    for (int kt = 0; kt < F0 / 32; kt++) {
        // load A tile [128 x 32] (coalesced float4, cvt to tf32)
        {
            bool valid = (bm0 + arow) < M;
            const float* gp = X + (size_t)(bm0 + arow) * F0 + kt * 32 + acol;
#pragma unroll
            for (int q = 0; q < 4; q++) {
                float4 v = valid ? *(const float4*)(gp + q * 4)
                                 : make_float4(0.f, 0.f, 0.f, 0.f);
                uint32_t* s = &sA[arow * SA_LD + acol + q * 4];
                s[0] = f2tf32(v.x); s[1] = f2tf32(v.y);
                s[2] = f2tf32(v.z); s[3] = f2tf32(v.w);
            }
        }
        // load B tile [32 x 128] (coalesced float4, cvt)
        {
            const float* gp = W + (size_t)(kt * 32 + brow) * C1 + bn0 + bcol;
#pragma unroll
            for (int q = 0; q < 4; q++) {
                float4 v = *(const float4*)(gp + q * 4);
                uint32_t* s = &sB[brow * SB_LD + bcol + q * 4];
                s[0] = f2tf32(v.x); s[1] = f2tf32(v.y);
                s[2] = f2tf32(v.z); s[3] = f2tf32(v.w);
            }
        }
        __syncthreads();

#pragma unroll
        for (int ks = 0; ks < 4; ks++) {
            const int kb = ks * 8;
            uint32_t af[4][4], bf[4][2];
#pragma unroll
            for (int mf = 0; mf < 4; mf++) {
                const uint32_t* ap = &sA[(warpM * 64 + mf * 16 + qid) * SA_LD + kb + tq];
                af[mf][0] = ap[0];
                af[mf][1] = ap[8 * SA_LD];
                af[mf][2] = ap[4];
                af[mf][3] = ap[8 * SA_LD + 4];
            }
#pragma unroll
            for (int nf = 0; nf < 4; nf++) {
                const uint32_t* bp = &sB[(kb + tq) * SB_LD + warpN * 32 + nf * 8 + qid];
                bf[nf][0] = bp[0];
                bf[nf][1] = bp[4 * SB_LD];
            }
#pragma unroll
            for (int mf = 0; mf < 4; mf++)
#pragma unroll
                for (int nf = 0; nf < 4; nf++)
                    mma_tf32(acc[mf][nf], af[mf], bf[nf]);
        }
        __syncthreads();
    }

    // epilogue: store XW + alpha partial dots
#pragma unroll
    for (int mf = 0; mf < 4; mf++) {
        int m_base = bm0 + warpM * 64 + mf * 16;
        int r0 = m_base + qid, r1 = m_base + qid + 8;
        float s0 = 0.f, d0 = 0.f, s1 = 0.f, d1 = 0.f;
#pragma unroll
        for (int nf = 0; nf < 4; nf++) {
            int lc = warpN * 32 + nf * 8 + 2 * tq;   // local col 0..127
            float as0 = sAs[lc], as1 = sAs[lc + 1];
            float ad0 = sAd[lc], ad1 = sAd[lc + 1];
            s0 += acc[mf][nf][0] * as0 + acc[mf][nf][1] * as1;
            d0 += acc[mf][nf][0] * ad0 + acc[mf][nf][1] * ad1;
            s1 += acc[mf][nf][2] * as0 + acc[mf][nf][3] * as1;
            d1 += acc[mf][nf][2] * ad0 + acc[mf][nf][3] * ad1;
            if (r0 < M)
                *(float2*)&XW[(size_t)r0 * C1 + bn0 + lc] =
                    make_float2(acc[mf][nf][0], acc[mf][nf][1]);
            if (r1 < M)
                *(float2*)&XW[(size_t)r1 * C1 + bn0 + lc] =
                    make_float2(acc[mf][nf][2], acc[mf][nf][3]);
        }
        // reduce over the 4 tq lanes
#pragma unroll
        for (int o = 1; o < 4; o <<= 1) {
            s0 += __shfl_xor_sync(0xffffffffu, s0, o);
            d0 += __shfl_xor_sync(0xffffffffu, d0, o);
            s1 += __shfl_xor_sync(0xffffffffu, s1, o);
            d1 += __shfl_xor_sync(0xffffffffu, d1, o);
        }
        if (tq == 0) {
            if (r0 < M) { atomicAdd(&g_as[r0], s0); atomicAdd(&g_ad[r0], d0); }
            if (r1 < M) { atomicAdd(&g_as[r1], s1); atomicAdd(&g_ad[r1], d1); }
        }
    }
}

// ============================================================================
// GEMM2 (mma.sync tf32): out = relu(relu(agg+b) @ W2 + b2) @ Wo + bo
// [M,256]x[256,128], fused 128->6 projection via smem reduce. grid.x=1.
// ============================================================================
__global__ void __launch_bounds__(256, 2)
gat_gemm2(const float* __restrict__ A, const float* __restrict__ W2,
          const float* __restrict__ bin, const float* __restrict__ b2p,
          const float* __restrict__ Wo, const float* __restrict__ bo,
          float* __restrict__ out, int M)
{
    __shared__ uint32_t sA[128 * SA_LD];
    __shared__ uint32_t sB[32 * SB_LD];
    __shared__ float sBias[C1];
    __shared__ float sB2[C2];
    __shared__ float sWo[C2 * NOUT];
    __shared__ float sOut[128 * NOUT];

    const int tid   = threadIdx.x;
    const int lane  = tid & 31;
    const int wid   = tid >> 5;
    const int qid   = lane >> 2;
    const int tq    = lane & 3;
    const int warpM = wid & 1;
    const int warpN = wid >> 1;
    const int bm0   = blockIdx.y * 128;

    if (tid < C1) sBias[tid] = bin[tid];
    if (tid < C2) sB2[tid] = b2p[tid];
    for (int i = tid; i < C2 * NOUT; i += 256) sWo[i] = Wo[i];
    for (int i = tid; i < 128 * NOUT; i += 256) sOut[i] = 0.f;

    float acc[4][4][4];
#pragma unroll
    for (int i = 0; i < 4; i++)
#pragma unroll
        for (int j = 0; j < 4; j++)
#pragma unroll
            for (int q = 0; q < 4; q++) acc[i][j][q] = 0.f;

    const int arow = tid >> 1, acol = (tid & 1) * 16;
    const int brow = tid >> 3, bcol = (tid & 7) * 16;

    __syncthreads();   // sBias ready before A-load uses it

    for (int kt = 0; kt < C1 / 32; kt++) {
        {
            bool valid = (bm0 + arow) < M;
            const float* gp = A + (size_t)(bm0 + arow) * C1 + kt * 32 + acol;
#pragma unroll
            for (int q = 0; q < 4; q++) {
                int kb = kt * 32 + acol + q * 4;
                float4 v = valid ? *(const float4*)(gp + q * 4)
                                 : make_float4(0.f, 0.f, 0.f, 0.f);
                v.x = fmaxf(v.x + sBias[kb + 0], 0.f);
                v.y = fmaxf(v.y + sBias[kb + 1], 0.f);
                v.z = fmaxf(v.z + sBias[kb + 2], 0.f);
                v.w = fmaxf(v.w + sBias[kb + 3], 0.f);
                uint32_t* s = &sA[arow * SA_LD + acol + q * 4];
                s[0] = f2tf32(v.x); s[1] = f2tf32(v.y);
                s[2] = f2tf32(v.z); s[3] = f2tf32(v.w);
            }
        }
        {
            const float* gp = W2 + (size_t)(kt * 32 + brow) * C2 + bcol;
#pragma unroll
            for (int q = 0; q < 4; q++) {
                float4 v = *(const float4*)(gp + q * 4);
                uint32_t* s = &sB[brow * SB_LD + bcol + q * 4];
                s[0] = f2tf32(v.x); s[1] = f2tf32(v.y);
                s[2] = f2tf32(v.z); s[3] = f2tf32(v.w);
            }
        }
        __syncthreads();

#pragma unroll
        for (int ks = 0; ks < 4; ks++) {
            const int kb = ks * 8;
            uint32_t af[4][4], bf[4][2];
#pragma unroll
            for (int mf = 0; mf < 4; mf++) {
                const uint32_t* ap = &sA[(warpM * 64 + mf * 16 + qid) * SA_LD + kb + tq];
                af[mf][0] = ap[0];
                af[mf][1] = ap[8 * SA_LD];
                af[mf][2] = ap[4];
                af[mf][3] = ap[8 * SA_LD + 4];
            }
#pragma unroll
            for (int nf = 0; nf < 4; nf++) {
                const uint32_t* bp = &sB[(kb + tq) * SB_LD + warpN * 32 + nf * 8 + qid];
                bf[nf][0] = bp[0];
                bf[nf][1] = bp[4 * SB_LD];
            }
#pragma unroll
            for (int mf = 0; mf < 4; mf++)
#pragma unroll
                for (int nf = 0; nf < 4; nf++)
                    mma_tf32(acc[mf][nf], af[mf], bf[nf]);
        }
        __syncthreads();
    }

    // epilogue: h = relu(acc + b2), project to 6 outputs into sOut
#pragma unroll
    for (int mf = 0; mf < 4; mf++) {
        int rl0 = warpM * 64 + mf * 16 + qid;   // local rows
        int rl1 = rl0 + 8;
        float po0[NOUT], po1[NOUT];
#pragma unroll
        for (int o = 0; o < NOUT; o++) { po0[o] = 0.f; po1[o] = 0.f; }
#pragma unroll
        for (int nf = 0; nf < 4; nf++) {
            int lc = warpN * 32 + nf * 8 + 2 * tq;
            float h00 = fmaxf(acc[mf][nf][0] + sB2[lc],     0.f);
            float h01 = fmaxf(acc[mf][nf][1] + sB2[lc + 1], 0.f);
            float h10 = fmaxf(acc[mf][nf][2] + sB2[lc],     0.f);
            float h11 = fmaxf(acc[mf][nf][3] + sB2[lc + 1], 0.f);
#pragma unroll
            for (int o = 0; o < NOUT; o++) {
                po0[o] += h00 * sWo[lc * NOUT + o] + h01 * sWo[(lc + 1) * NOUT + o];
                po1[o] += h10 * sWo[lc * NOUT + o] + h11 * sWo[(lc + 1) * NOUT + o];
            }
        }
#pragma unroll
        for (int o = 0; o < NOUT; o++) {
#pragma unroll
            for (int sft = 1; sft < 4; sft <<= 1) {
                po0[o] += __shfl_xor_sync(0xffffffffu, po0[o], sft);
                po1[o] += __shfl_xor_sync(0xffffffffu, po1[o], sft);
            }
        }
        if (tq == 0) {
#pragma unroll
            for (int o = 0; o < NOUT; o++) {
                atomicAdd(&sOut[rl0 * NOUT + o], po0[o]);
                atomicAdd(&sOut[rl1 * NOUT + o], po1[o]);
            }
        }
    }
    __syncthreads();
    for (int i = tid; i < 128 * NOUT; i += 256) {
        int rl = i / NOUT, o = i % NOUT;
        int row = bm0 + rl;
        if (row < M) out[(size_t)row * NOUT + o] = sOut[i] + bo[o];
    }
}

// ---------------- edge pass 1: weight + denom (no max: scores are tiny) -----
__global__ void edge_weights(const int* __restrict__ ei, int E, int n)
{
    int i = blockIdx.x * blockDim.x + threadIdx.x;
    if (i >= E + n) return;
    int s, d;
    if (i < E) { s = __ldg(&ei[i]); d = __ldg(&ei[E + i]); } else { s = d = i - E; }
    float e = g_as[s] + g_ad[d];
    e = e > 0.f ? e : 0.2f * e;          // LeakyReLU(0.2)
    float w = __expf(e);
    g_e[i] = w;
    atomicAdd(&g_den[d], w);
}

// ---------------- edge pass 2: weighted scatter (1 warp / edge) -------------
__global__ void edge_scatter(const int* __restrict__ ei, int E, int n)
{
    int warp = (int)(((size_t)blockIdx.x * blockDim.x + threadIdx.x) >> 5);
    int lane = threadIdx.x & 31;
    if (warp >= E + n) return;
    int s, d;
    float w;
    if (lane == 0) {
        if (warp < E) { s = __ldg(&ei[warp]); d = __ldg(&ei[E + warp]); }
        else          { s = d = warp - E; }
        w = g_e[warp] / g_den[d];
    }
    s = __shfl_sync(0xffffffffu, s, 0);
    d = __shfl_sync(0xffffffffu, d, 0);
    w = __shfl_sync(0xffffffffu, w, 0);
    const float4* src = (const float4*)&g_xw[(size_t)s * C1];
    float*        dp  = &g_agg[(size_t)d * C1];
#pragma unroll
    for (int h = 0; h < 2; h++) {
        float4 v = src[lane + h * 32];
        float* p = dp + (size_t)(lane + h * 32) * 4;
        asm volatile("red.global.add.v4.f32 [%0], {%1,%2,%3,%4};"
                     :: "l"(p), "f"(v.x * w), "f"(v.y * w),
                        "f"(v.z * w), "f"(v.w * w)
                     : "memory");
    }
}

// ---------------- launch ----------------------------------------------------
extern "C" void kernel_launch(void* const* d_in, const int* in_sizes, int n_in,
                              void* d_out, int out_size)
{
    const float* x     = (const float*)d_in[0];
    const int*   ei    = (const int*)  d_in[1];
    const float* W     = (const float*)d_in[2];
    const float* a_src = (const float*)d_in[3];
    const float* a_dst = (const float*)d_in[4];
    const float* b     = (const float*)d_in[5];
    const float* W2    = (const float*)d_in[6];
    const float* b2    = (const float*)d_in[7];
    const float* Wo    = (const float*)d_in[8];
    const float* bo    = (const float*)d_in[9];

    const int n = in_sizes[0] / F0;   // 100000
    const int E = in_sizes[1] / 2;    // 800000
    const int tot = E + n;

    float *xw, *agg, *as_, *ad_, *den;
    cudaGetSymbolAddress((void**)&xw,  g_xw);
    cudaGetSymbolAddress((void**)&agg, g_agg);
    cudaGetSymbolAddress((void**)&as_, g_as);
    cudaGetSymbolAddress((void**)&ad_, g_ad);
    cudaGetSymbolAddress((void**)&den, g_den);

    // zero accumulators (async memsets are graph-capturable)
    cudaMemsetAsync(agg, 0, (size_t)n * C1 * sizeof(float));
    cudaMemsetAsync(as_, 0, (size_t)n * sizeof(float));
    cudaMemsetAsync(ad_, 0, (size_t)n * sizeof(float));
    cudaMemsetAsync(den, 0, (size_t)n * sizeof(float));

    // GEMM1 (mma.sync tf32) + fused alpha
    {
        dim3 grid(C1 / 128, (n + 127) / 128);
        gat_gemm1<<<grid, 256>>>(x, W, a_src, a_dst, xw, n);
    }
    // edge softmax weights + denom
    edge_weights<<<(tot + 255) / 256, 256>>>(ei, E, n);
    // weighted scatter aggregate (1 warp per edge)
    {
        size_t threads = (size_t)tot * 32;
        edge_scatter<<<(unsigned)((threads + 255) / 256), 256>>>(ei, E, n);
    }
    // GEMM2 (mma.sync tf32) + fused output projection (writes d_out directly)
    {
        dim3 grid(1, (n + 127) / 128);
        gat_gemm2<<<grid, 256>>>(agg, W2, b, b2, Wo, bo, (float*)d_out, n);
    }
}

// round 9
// speedup vs baseline: 2.1821x; 1.5157x over previous
#include <cuda_runtime.h>
#include <cstdint>

#define NN   100000
#define NE   800000
#define F0   128
#define C1   256
#define C2   128
#define NOUT 6

// ---------------- scratch (device globals: allocation-free rule) ------------
__device__ float g_xw [(size_t)NN * C1];
__device__ float g_agg[(size_t)NN * C1];
__device__ float g_as [NN];
__device__ float g_ad [NN];
__device__ float g_den[NN];
__device__ float g_e  [NN + NE];
__device__ int   g_deg[NN];
__device__ int   g_rowptr[NN];
__device__ int   g_cur[NN];
__device__ int   g_bsum[256];
__device__ int2  g_edges[NN + NE];

// ---------------- tf32 helpers ----------------------------------------------
__device__ __forceinline__ uint32_t f2tf32(float f) {
    uint32_t u;
    asm("cvt.rna.tf32.f32 %0, %1;" : "=r"(u) : "f"(f));
    return u;
}
__device__ __forceinline__ void mma_tf32(float* c, const uint32_t* a, const uint32_t* b) {
    asm volatile(
        "mma.sync.aligned.m16n8k8.row.col.f32.tf32.tf32.f32 "
        "{%0,%1,%2,%3}, {%4,%5,%6,%7}, {%8,%9}, {%0,%1,%2,%3};"
        : "+f"(c[0]), "+f"(c[1]), "+f"(c[2]), "+f"(c[3])
        : "r"(a[0]), "r"(a[1]), "r"(a[2]), "r"(a[3]), "r"(b[0]), "r"(b[1]));
}

#define SA_LD 36
#define SB_LD 136

// ============================================================================
// GEMM1 (mma.sync tf32): xw = x @ W  [M,128]x[128,256] + fused alpha partials
// ============================================================================
__global__ void __launch_bounds__(256, 2)
gat_gemm1(const float* __restrict__ X, const float* __restrict__ W,
          const float* __restrict__ a_srcp, const float* __restrict__ a_dstp,
          float* __restrict__ XW, int M)
{
    __shared__ uint32_t sA[128 * SA_LD];
    __shared__ uint32_t sB[32 * SB_LD];
    __shared__ float sAs[128], sAd[128];

    const int tid   = threadIdx.x;
    const int lane  = tid & 31;
    const int wid   = tid >> 5;
    const int qid   = lane >> 2;
    const int tq    = lane & 3;
    const int warpM = wid & 1;
    const int warpN = wid >> 1;
    const int bm0   = blockIdx.y * 128;
    const int bn0   = blockIdx.x * 128;

    if (tid < 128) { sAs[tid] = a_srcp[bn0 + tid]; sAd[tid] = a_dstp[bn0 + tid]; }

    float acc[4][4][4];
#pragma unroll
    for (int i = 0; i < 4; i++)
#pragma unroll
        for (int j = 0; j < 4; j++)
#pragma unroll
            for (int q = 0; q < 4; q++) acc[i][j][q] = 0.f;

    const int arow = tid >> 1, acol = (tid & 1) * 16;
    const int brow = tid >> 3, bcol = (tid & 7) * 16;

    for (int kt = 0; kt < F0 / 32; kt++) {
        {
            bool valid = (bm0 + arow) < M;
            const float* gp = X + (size_t)(bm0 + arow) * F0 + kt * 32 + acol;
#pragma unroll
            for (int q = 0; q < 4; q++) {
                float4 v = valid ? *(const float4*)(gp + q * 4)
                                 : make_float4(0.f, 0.f, 0.f, 0.f);
                uint32_t* s = &sA[arow * SA_LD + acol + q * 4];
                s[0] = f2tf32(v.x); s[1] = f2tf32(v.y);
                s[2] = f2tf32(v.z); s[3] = f2tf32(v.w);
            }
        }
        {
            const float* gp = W + (size_t)(kt * 32 + brow) * C1 + bn0 + bcol;
#pragma unroll
            for (int q = 0; q < 4; q++) {
                float4 v = *(const float4*)(gp + q * 4);
                uint32_t* s = &sB[brow * SB_LD + bcol + q * 4];
                s[0] = f2tf32(v.x); s[1] = f2tf32(v.y);
                s[2] = f2tf32(v.z); s[3] = f2tf32(v.w);
            }
        }
        __syncthreads();

#pragma unroll
        for (int ks = 0; ks < 4; ks++) {
            const int kb = ks * 8;
            uint32_t af[4][4], bf[4][2];
#pragma unroll
            for (int mf = 0; mf < 4; mf++) {
                const uint32_t* ap = &sA[(warpM * 64 + mf * 16 + qid) * SA_LD + kb + tq];
                af[mf][0] = ap[0];
                af[mf][1] = ap[8 * SA_LD];
                af[mf][2] = ap[4];
                af[mf][3] = ap[8 * SA_LD + 4];
            }
#pragma unroll
            for (int nf = 0; nf < 4; nf++) {
                const uint32_t* bp = &sB[(kb + tq) * SB_LD + warpN * 32 + nf * 8 + qid];
                bf[nf][0] = bp[0];
                bf[nf][1] = bp[4 * SB_LD];
            }
#pragma unroll
            for (int mf = 0; mf < 4; mf++)
#pragma unroll
                for (int nf = 0; nf < 4; nf++)
                    mma_tf32(acc[mf][nf], af[mf], bf[nf]);
        }
        __syncthreads();
    }

#pragma unroll
    for (int mf = 0; mf < 4; mf++) {
        int m_base = bm0 + warpM * 64 + mf * 16;
        int r0 = m_base + qid, r1 = m_base + qid + 8;
        float s0 = 0.f, d0 = 0.f, s1 = 0.f, d1 = 0.f;
#pragma unroll
        for (int nf = 0; nf < 4; nf++) {
            int lc = warpN * 32 + nf * 8 + 2 * tq;
            float as0 = sAs[lc], as1 = sAs[lc + 1];
            float ad0 = sAd[lc], ad1 = sAd[lc + 1];
            s0 += acc[mf][nf][0] * as0 + acc[mf][nf][1] * as1;
            d0 += acc[mf][nf][0] * ad0 + acc[mf][nf][1] * ad1;
            s1 += acc[mf][nf][2] * as0 + acc[mf][nf][3] * as1;
            d1 += acc[mf][nf][2] * ad0 + acc[mf][nf][3] * ad1;
            if (r0 < M)
                *(float2*)&XW[(size_t)r0 * C1 + bn0 + lc] =
                    make_float2(acc[mf][nf][0], acc[mf][nf][1]);
            if (r1 < M)
                *(float2*)&XW[(size_t)r1 * C1 + bn0 + lc] =
                    make_float2(acc[mf][nf][2], acc[mf][nf][3]);
        }
#pragma unroll
        for (int o = 1; o < 4; o <<= 1) {
            s0 += __shfl_xor_sync(0xffffffffu, s0, o);
            d0 += __shfl_xor_sync(0xffffffffu, d0, o);
            s1 += __shfl_xor_sync(0xffffffffu, s1, o);
            d1 += __shfl_xor_sync(0xffffffffu, d1, o);
        }
        if (tq == 0) {
            if (r0 < M) { atomicAdd(&g_as[r0], s0); atomicAdd(&g_ad[r0], d0); }
            if (r1 < M) { atomicAdd(&g_as[r1], s1); atomicAdd(&g_ad[r1], d1); }
        }
    }
}

// ============================================================================
// GEMM2 (mma.sync tf32): out = relu(relu(agg+b) @ W2 + b2) @ Wo + bo
// ============================================================================
__global__ void __launch_bounds__(256, 2)
gat_gemm2(const float* __restrict__ A, const float* __restrict__ W2,
          const float* __restrict__ bin, const float* __restrict__ b2p,
          const float* __restrict__ Wo, const float* __restrict__ bo,
          float* __restrict__ out, int M)
{
    __shared__ uint32_t sA[128 * SA_LD];
    __shared__ uint32_t sB[32 * SB_LD];
    __shared__ float sBias[C1];
    __shared__ float sB2[C2];
    __shared__ float sWo[C2 * NOUT];
    __shared__ float sOut[128 * NOUT];

    const int tid   = threadIdx.x;
    const int lane  = tid & 31;
    const int wid   = tid >> 5;
    const int qid   = lane >> 2;
    const int tq    = lane & 3;
    const int warpM = wid & 1;
    const int warpN = wid >> 1;
    const int bm0   = blockIdx.y * 128;

    if (tid < C1) sBias[tid] = bin[tid];
    if (tid < C2) sB2[tid] = b2p[tid];
    for (int i = tid; i < C2 * NOUT; i += 256) sWo[i] = Wo[i];
    for (int i = tid; i < 128 * NOUT; i += 256) sOut[i] = 0.f;

    float acc[4][4][4];
#pragma unroll
    for (int i = 0; i < 4; i++)
#pragma unroll
        for (int j = 0; j < 4; j++)
#pragma unroll
            for (int q = 0; q < 4; q++) acc[i][j][q] = 0.f;

    const int arow = tid >> 1, acol = (tid & 1) * 16;
    const int brow = tid >> 3, bcol = (tid & 7) * 16;

    __syncthreads();

    for (int kt = 0; kt < C1 / 32; kt++) {
        {
            bool valid = (bm0 + arow) < M;
            const float* gp = A + (size_t)(bm0 + arow) * C1 + kt * 32 + acol;
#pragma unroll
            for (int q = 0; q < 4; q++) {
                int kb = kt * 32 + acol + q * 4;
                float4 v = valid ? *(const float4*)(gp + q * 4)
                                 : make_float4(0.f, 0.f, 0.f, 0.f);
                v.x = fmaxf(v.x + sBias[kb + 0], 0.f);
                v.y = fmaxf(v.y + sBias[kb + 1], 0.f);
                v.z = fmaxf(v.z + sBias[kb + 2], 0.f);
                v.w = fmaxf(v.w + sBias[kb + 3], 0.f);
                uint32_t* s = &sA[arow * SA_LD + acol + q * 4];
                s[0] = f2tf32(v.x); s[1] = f2tf32(v.y);
                s[2] = f2tf32(v.z); s[3] = f2tf32(v.w);
            }
        }
        {
            const float* gp = W2 + (size_t)(kt * 32 + brow) * C2 + bcol;
#pragma unroll
            for (int q = 0; q < 4; q++) {
                float4 v = *(const float4*)(gp + q * 4);
                uint32_t* s = &sB[brow * SB_LD + bcol + q * 4];
                s[0] = f2tf32(v.x); s[1] = f2tf32(v.y);
                s[2] = f2tf32(v.z); s[3] = f2tf32(v.w);
            }
        }
        __syncthreads();

#pragma unroll
        for (int ks = 0; ks < 4; ks++) {
            const int kb = ks * 8;
            uint32_t af[4][4], bf[4][2];
#pragma unroll
            for (int mf = 0; mf < 4; mf++) {
                const uint32_t* ap = &sA[(warpM * 64 + mf * 16 + qid) * SA_LD + kb + tq];
                af[mf][0] = ap[0];
                af[mf][1] = ap[8 * SA_LD];
                af[mf][2] = ap[4];
                af[mf][3] = ap[8 * SA_LD + 4];
            }
#pragma unroll
            for (int nf = 0; nf < 4; nf++) {
                const uint32_t* bp = &sB[(kb + tq) * SB_LD + warpN * 32 + nf * 8 + qid];
                bf[nf][0] = bp[0];
                bf[nf][1] = bp[4 * SB_LD];
            }
#pragma unroll
            for (int mf = 0; mf < 4; mf++)
#pragma unroll
                for (int nf = 0; nf < 4; nf++)
                    mma_tf32(acc[mf][nf], af[mf], bf[nf]);
        }
        __syncthreads();
    }

#pragma unroll
    for (int mf = 0; mf < 4; mf++) {
        int rl0 = warpM * 64 + mf * 16 + qid;
        int rl1 = rl0 + 8;
        float po0[NOUT], po1[NOUT];
#pragma unroll
        for (int o = 0; o < NOUT; o++) { po0[o] = 0.f; po1[o] = 0.f; }
#pragma unroll
        for (int nf = 0; nf < 4; nf++) {
            int lc = warpN * 32 + nf * 8 + 2 * tq;
            float h00 = fmaxf(acc[mf][nf][0] + sB2[lc],     0.f);
            float h01 = fmaxf(acc[mf][nf][1] + sB2[lc + 1], 0.f);
            float h10 = fmaxf(acc[mf][nf][2] + sB2[lc],     0.f);
            float h11 = fmaxf(acc[mf][nf][3] + sB2[lc + 1], 0.f);
#pragma unroll
            for (int o = 0; o < NOUT; o++) {
                po0[o] += h00 * sWo[lc * NOUT + o] + h01 * sWo[(lc + 1) * NOUT + o];
                po1[o] += h10 * sWo[lc * NOUT + o] + h11 * sWo[(lc + 1) * NOUT + o];
            }
        }
#pragma unroll
        for (int o = 0; o < NOUT; o++) {
#pragma unroll
            for (int sft = 1; sft < 4; sft <<= 1) {
                po0[o] += __shfl_xor_sync(0xffffffffu, po0[o], sft);
                po1[o] += __shfl_xor_sync(0xffffffffu, po1[o], sft);
            }
        }
        if (tq == 0) {
#pragma unroll
            for (int o = 0; o < NOUT; o++) {
                atomicAdd(&sOut[rl0 * NOUT + o], po0[o]);
                atomicAdd(&sOut[rl1 * NOUT + o], po1[o]);
            }
        }
    }
    __syncthreads();
    for (int i = tid; i < 128 * NOUT; i += 256) {
        int rl = i / NOUT, o = i % NOUT;
        int row = bm0 + rl;
        if (row < M) out[(size_t)row * NOUT + o] = sOut[i] + bo[o];
    }
}

// ---------------- edge pass: weight + denom + degree histogram --------------
__global__ void edge_weights(const int* __restrict__ ei, int E, int n)
{
    int i = blockIdx.x * blockDim.x + threadIdx.x;
    if (i >= E + n) return;
    int s, d;
    if (i < E) { s = __ldg(&ei[i]); d = __ldg(&ei[E + i]); } else { s = d = i - E; }
    float e = g_as[s] + g_ad[d];
    e = e > 0.f ? e : 0.2f * e;          // LeakyReLU(0.2)
    float w = __expf(e);
    g_e[i] = w;
    atomicAdd(&g_den[d], w);
    atomicAdd(&g_deg[d], 1);
}

// ---------------- CSR scan (3 small kernels) --------------------------------
#define SCB 512
__global__ void scan1(int n)
{
    __shared__ int s[SCB];
    int tid = threadIdx.x;
    int i = blockIdx.x * SCB + tid;
    int v = (i < n) ? g_deg[i] : 0;
    s[tid] = v; __syncthreads();
#pragma unroll
    for (int off = 1; off < SCB; off <<= 1) {
        int t = (tid >= off) ? s[tid - off] : 0;
        __syncthreads();
        s[tid] += t;
        __syncthreads();
    }
    if (i < n) g_rowptr[i] = s[tid] - v;
    if (tid == SCB - 1) g_bsum[blockIdx.x] = s[tid];
}
__global__ void scan2(int nb)
{
    __shared__ int s[256];
    int tid = threadIdx.x;
    int v = (tid < nb) ? g_bsum[tid] : 0;
    s[tid] = v; __syncthreads();
#pragma unroll
    for (int off = 1; off < 256; off <<= 1) {
        int t = (tid >= off) ? s[tid - off] : 0;
        __syncthreads();
        s[tid] += t;
        __syncthreads();
    }
    if (tid < nb) g_bsum[tid] = s[tid] - v;
}
__global__ void scan3(int n)
{
    int i = blockIdx.x * blockDim.x + threadIdx.x;
    if (i >= n) return;
    int r = g_rowptr[i] + g_bsum[i / SCB];
    g_rowptr[i] = r;
    g_cur[i] = r;
}

// ---------------- fill packed CSR edges (src, weight) -----------------------
__global__ void fill_csr(const int* __restrict__ ei, int E, int n)
{
    int i = blockIdx.x * blockDim.x + threadIdx.x;
    if (i >= E + n) return;
    int s, d;
    if (i < E) { s = __ldg(&ei[i]); d = __ldg(&ei[E + i]); } else { s = d = i - E; }
    float w = g_e[i] / g_den[d];
    int pos = atomicAdd(&g_cur[d], 1);
    g_edges[pos] = make_int2(s, __float_as_int(w));
}

// ---------------- aggregate: warp per dst, no atomics -----------------------
__global__ void aggregate(int n)
{
    int warp = (int)(((size_t)blockIdx.x * blockDim.x + threadIdx.x) >> 5);
    int lane = threadIdx.x & 31;
    if (warp >= n) return;
    int start = g_rowptr[warp];
    int deg   = g_deg[warp];
    const float4* xw4 = (const float4*)g_xw;
    float4 a0 = make_float4(0.f, 0.f, 0.f, 0.f);
    float4 a1 = make_float4(0.f, 0.f, 0.f, 0.f);
    for (int k = 0; k < deg; k++) {
        int2 e = __ldg(&g_edges[start + k]);
        float w = __int_as_float(e.y);
        const float4* src = &xw4[(size_t)e.x * 64];
        float4 v0 = __ldg(&src[lane]);
        float4 v1 = __ldg(&src[lane + 32]);
        a0.x += w * v0.x; a0.y += w * v0.y; a0.z += w * v0.z; a0.w += w * v0.w;
        a1.x += w * v1.x; a1.y += w * v1.y; a1.z += w * v1.z; a1.w += w * v1.w;
    }
    float4* dst = (float4*)&g_agg[(size_t)warp * C1];
    dst[lane]      = a0;
    dst[lane + 32] = a1;
}

// ---------------- launch ----------------------------------------------------
extern "C" void kernel_launch(void* const* d_in, const int* in_sizes, int n_in,
                              void* d_out, int out_size)
{
    const float* x     = (const float*)d_in[0];
    const int*   ei    = (const int*)  d_in[1];
    const float* W     = (const float*)d_in[2];
    const float* a_src = (const float*)d_in[3];
    const float* a_dst = (const float*)d_in[4];
    const float* b     = (const float*)d_in[5];
    const float* W2    = (const float*)d_in[6];
    const float* b2    = (const float*)d_in[7];
    const float* Wo    = (const float*)d_in[8];
    const float* bo    = (const float*)d_in[9];

    const int n = in_sizes[0] / F0;   // 100000
    const int E = in_sizes[1] / 2;    // 800000
    const int tot = E + n;
    const int nb = (n + SCB - 1) / SCB;

    float *xw, *agg, *as_, *ad_, *den;
    int *deg;
    cudaGetSymbolAddress((void**)&xw,  g_xw);
    cudaGetSymbolAddress((void**)&agg, g_agg);
    cudaGetSymbolAddress((void**)&as_, g_as);
    cudaGetSymbolAddress((void**)&ad_, g_ad);
    cudaGetSymbolAddress((void**)&den, g_den);
    cudaGetSymbolAddress((void**)&deg, g_deg);

    cudaMemsetAsync(as_, 0, (size_t)n * sizeof(float));
    cudaMemsetAsync(ad_, 0, (size_t)n * sizeof(float));
    cudaMemsetAsync(den, 0, (size_t)n * sizeof(float));
    cudaMemsetAsync(deg, 0, (size_t)n * sizeof(int));

    // GEMM1 + fused alpha
    {
        dim3 grid(C1 / 128, (n + 127) / 128);
        gat_gemm1<<<grid, 256>>>(x, W, a_src, a_dst, xw, n);
    }
    // edge softmax weights + denom + degree
    edge_weights<<<(tot + 255) / 256, 256>>>(ei, E, n);
    // CSR build
    scan1<<<nb, SCB>>>(n);
    scan2<<<1, 256>>>(nb);
    scan3<<<(n + 255) / 256, 256>>>(n);
    fill_csr<<<(tot + 255) / 256, 256>>>(ei, E, n);
    // aggregate (warp per dst, no atomics)
    {
        size_t threads = (size_t)n * 32;
        aggregate<<<(unsigned)((threads + 255) / 256), 256>>>(n);
    }
    // GEMM2 + fused output projection
    {
        dim3 grid(1, (n + 127) / 128);
        gat_gemm2<<<grid, 256>>>(agg, W2, b, b2, Wo, bo, (float*)d_out, n);
    }
}